// round 4
// baseline (speedup 1.0000x reference)
#include <cuda_runtime.h>
#include <math.h>

// ---------------- constants ----------------
#define NB_B 8
constexpr int NBATCH = 2048;
constexpr int CGTOT  = 531;
constexpr int NCH    = 5888;
constexpr int NW     = 94208;

// combo tables (l1,l2,l) in reference TRIPLES order, grouped by output l
__constant__ int c_l1[23]  = {0,1,2,3, 1,1,2,2,3,3, 1,2,2,2,3,3,3, 2,2,3,3,3,3};
__constant__ int c_l2[23]  = {0,1,2,3, 0,1,1,2,2,3, 1,0,1,2,1,2,3, 1,2,0,1,2,3};
__constant__ int c_lo[23]  = {0,0,0,0, 1,1,1,1,1,1, 2,2,2,2,2,2,2, 3,3,3,3,3,3};
__constant__ int c_off[23] = {0,1,10,35, 84,87,96,111,136,171,
                              220,229,234,249,274,295,330, 379,394,419,426,447,482};

__device__ float  g_cg[CGTOT];
__device__ float  g_sumsq[NCH];
__device__ float2 g_wt[NW];   // folded, transposed weights: [l-block][c][o]

__host__ __device__ constexpr int AOFF(int l){ return l==0?0 : l==1?16 : l==2?64 : 144; }

// ---------------- CG coefficient init (on device, fp64) ----------------
__device__ double d_fact(int n){ double r=1.0; for(int i=2;i<=n;++i) r*=(double)i; return r; }

__device__ double d_cg(int l1,int m1,int l2,int m2,int l,int m){
    if (m1+m2!=m) return 0.0;
    double pre = sqrt((double)(2*l+1)*d_fact(l1+l2-l)*d_fact(l1-l2+l)*d_fact(-l1+l2+l)/d_fact(l1+l2+l+1));
    pre *= sqrt(d_fact(l+m)*d_fact(l-m)*d_fact(l1-m1)*d_fact(l1+m1)*d_fact(l2-m2)*d_fact(l2+m2));
    double s=0.0;
    for(int k=0;k<=l1+l2-l;++k){
        int d0=k,d1=l1+l2-l-k,d2=l1-m1-k,d3=l2+m2-k,d4=l-l2+m1+k,d5=l-l1-m2+k;
        if(d0<0||d1<0||d2<0||d3<0||d4<0||d5<0) continue;
        double den=d_fact(d0)*d_fact(d1)*d_fact(d2)*d_fact(d3)*d_fact(d4)*d_fact(d5);
        s += ((k&1)? -1.0 : 1.0)/den;
    }
    return pre*s;
}

__global__ void init_cg(){
    int k = blockIdx.x;
    int l1=c_l1[k], l2=c_l2[k], l=c_lo[k];
    int n1=2*l1+1, n2=2*l2+1;
    for(int e=threadIdx.x; e<n1*n2; e+=blockDim.x){
        int m1=e/n2 - l1, m2=e%n2 - l2, m=m1+m2;
        float v=0.f;
        if (m>=-l && m<=l) v=(float)d_cg(l1,m1,l2,m2,l,m);
        g_cg[c_off[k]+e]=v;
    }
}

__global__ void zero_sumsq(){
    int i=blockIdx.x*blockDim.x+threadIdx.x;
    if(i<NCH) g_sumsq[i]=0.f;
}

// ---------------- mid tensor for one (t,s) channel, compile-time unrolled ----------------
template<int L1,int L2,int LO>
__device__ __forceinline__ void mid_ts(const float2* __restrict__ a1,
                                       const float2* __restrict__ a2,
                                       const float* __restrict__ cg,
                                       float2 (&acc)[2*LO+1]){
    float2 f1[2*L1+1], f2[2*L2+1];
#pragma unroll
    for(int i=0;i<2*L1+1;++i) f1[i]=a1[i];
#pragma unroll
    for(int j=0;j<2*L2+1;++j) f2[j]=a2[j];
#pragma unroll
    for(int p=0;p<2*LO+1;++p) acc[p]=make_float2(0.f,0.f);
#pragma unroll
    for(int i=0;i<2*L1+1;++i){
#pragma unroll
        for(int j=0;j<2*L2+1;++j){
            int m=(i-L1)+(j-L2);
            if (m < -LO || m > LO) continue;
            int p=m+LO;
            float c = cg[i*(2*L2+1)+j];
            float tr = f1[i].x*f2[j].x - f1[i].y*f2[j].y;
            float ti = f1[i].x*f2[j].y + f1[i].y*f2[j].x;
            acc[p].x = fmaf(c,tr,acc[p].x);
            acc[p].y = fmaf(c,ti,acc[p].y);
        }
    }
}

// ---------------- phase 1: per-channel sum of |mid|^2 over batch & p ----------------
__global__ __launch_bounds__(256) void k_sumsq(const float2* __restrict__ act){
    __shared__ float2 sAct[NB_B*256];
    __shared__ float  sCg[CGTOT];
    const int tid=threadIdx.x, t=tid>>4, s=tid&15;
    const float2* A = act + (size_t)blockIdx.x*NB_B*256;
    for(int i=tid;i<NB_B*256;i+=256) sAct[i]=A[i];
    for(int i=tid;i<CGTOT;i+=256)    sCg[i]=g_cg[i];
    __syncthreads();

#define SQC(L1,L2,LO,CGOFF,CH0) do{                                            \
    float ssum=0.f;                                                            \
    _Pragma("unroll 1")                                                        \
    for(int b=0;b<NB_B;++b){                                                   \
        const float2* Ab=sAct+b*256;                                           \
        float2 acc[2*(LO)+1];                                                  \
        mid_ts<L1,L2,LO>(Ab+AOFF(L1)+t*(2*(L1)+1),                             \
                         Ab+AOFF(L2)+s*(2*(L2)+1), sCg+(CGOFF), acc);          \
        _Pragma("unroll")                                                      \
        for(int p=0;p<2*(LO)+1;++p) ssum += acc[p].x*acc[p].x+acc[p].y*acc[p].y;\
    }                                                                          \
    atomicAdd(&g_sumsq[(CH0)+t*16+s], ssum);                                   \
}while(0)

    // l=0 (ch base 0)
    SQC(0,0,0,0,0);     SQC(1,1,0,1,256);   SQC(2,2,0,10,512);  SQC(3,3,0,35,768);
    // l=1 (ch base 1024)
    SQC(1,0,1,84,1024); SQC(1,1,1,87,1280); SQC(2,1,1,96,1536);
    SQC(2,2,1,111,1792);SQC(3,2,1,136,2048);SQC(3,3,1,171,2304);
    // l=2 (ch base 2560)
    SQC(1,1,2,220,2560);SQC(2,0,2,229,2816);SQC(2,1,2,234,3072);SQC(2,2,2,249,3328);
    SQC(3,1,2,274,3584);SQC(3,2,2,295,3840);SQC(3,3,2,330,4096);
    // l=3 (ch base 4352)
    SQC(2,1,3,379,4352);SQC(2,2,3,394,4608);SQC(3,0,3,419,4864);
    SQC(3,1,3,426,5120);SQC(3,2,3,447,5376);SQC(3,3,3,482,5632);
#undef SQC
}

// ---------------- phase 2: fold batchnorm std into W, transpose to [c][o] ----------------
__global__ void k_prep_w(const float2* __restrict__ W, const float* __restrict__ bn){
    int w = blockIdx.x*blockDim.x+threadIdx.x;
    if (w>=NW) return;
    int l,wst,sst,Ml;
    if      (w<16384){l=0;wst=0;    sst=0;   Ml=1024;}
    else if (w<40960){l=1;wst=16384;sst=1024;Ml=1536;}
    else if (w<69632){l=2;wst=40960;sst=2560;Ml=1792;}
    else             {l=3;wst=69632;sst=4352;Ml=1536;}
    int r=w-wst, o=r/Ml, c=r%Ml;
    float bstd = sqrtf(g_sumsq[sst+c]/(float)(NBATCH*(2*l+1)));
    float nstd = (bn[sst+c]*1.0f + bstd)*0.5f;          // BM_CNT = 1
    float inv  = 1.0f/(nstd + 1e-5f);
    float2 wv = W[w];
    g_wt[wst + c*16 + o] = make_float2(wv.x*inv, wv.y*inv);
}

// ---------------- phase 2: main fused kernel ----------------
template<int LO,int NPAIR>
__device__ __forceinline__ void matmul_l(const float2* __restrict__ sMid,
                                         float2* sPart,
                                         const float2* __restrict__ wt,
                                         float2* __restrict__ outp, int tid){
    constexpr int NP = 2*LO+1;
    constexpr int CN = NPAIR*256/16;
    const int o = tid&15, g = tid>>4;
    float2 acc[NP];
#pragma unroll
    for(int p=0;p<NP;++p) acc[p]=make_float2(0.f,0.f);
    const float2* w = wt + (size_t)(g*CN)*16 + o;
    const float2* m = sMid + (size_t)(g*CN)*NP;
#pragma unroll 4
    for(int c=0;c<CN;++c){
        float2 wv = w[c*16];
#pragma unroll
        for(int p=0;p<NP;++p){
            float2 mv = m[c*NP+p];
            acc[p].x = fmaf(wv.x,mv.x,fmaf(-wv.y,mv.y,acc[p].x));
            acc[p].y = fmaf(wv.x,mv.y,fmaf( wv.y,mv.x,acc[p].y));
        }
    }
#pragma unroll
    for(int p=0;p<NP;++p) sPart[(g*16+o)*NP+p]=acc[p];
    __syncthreads();
    if (tid < 16*NP){
        int oo=tid/NP, pp=tid%NP;
        float2 r=make_float2(0.f,0.f);
#pragma unroll
        for(int g2=0;g2<16;++g2){
            float2 v=sPart[(g2*16+oo)*NP+pp];
            r.x+=v.x; r.y+=v.y;
        }
        outp[oo*NP+pp]=r;
    }
    __syncthreads();
}

constexpr int SMEM_D_FLOATS = 512 + 532 + 2*10752 + 2*1792; // act, cg, mid(max l=3), partials
constexpr int SMEM_D_BYTES  = SMEM_D_FLOATS*4;              // 104,528 B

__global__ __launch_bounds__(256,2) void k_main(const float2* __restrict__ act,
                                                float2* __restrict__ out){
    extern __shared__ float dyn[];
    float2* sAct  = (float2*)dyn;             // 256 cplx
    float*  sCg   = dyn + 512;                // 531 (+1 pad)
    float2* sMid  = (float2*)(dyn + 512 + 532); // up to 1792*7... (max 1536*7=10752 cplx)
    float2* sPart = sMid + 10752;             // 16*16*7 cplx
    const int tid=threadIdx.x, t=tid>>4, s=tid&15;
    sAct[tid] = act[(size_t)blockIdx.x*256 + tid];
    for(int i=tid;i<CGTOT;i+=256) sCg[i]=g_cg[i];
    __syncthreads();
    float2* o2 = out + (size_t)blockIdx.x*256;

#define MIDC(L1,L2,LO,CGOFF,PAIR) do{                                          \
    float2 acc[2*(LO)+1];                                                      \
    mid_ts<L1,L2,LO>(sAct+AOFF(L1)+t*(2*(L1)+1),                               \
                     sAct+AOFF(L2)+s*(2*(L2)+1), sCg+(CGOFF), acc);            \
    float2* mp=sMid+((PAIR)*256+(t*16+s))*(2*(LO)+1);                          \
    _Pragma("unroll")                                                          \
    for(int p=0;p<2*(LO)+1;++p) mp[p]=acc[p];                                  \
}while(0)

    // ---- l = 0 ----
    MIDC(0,0,0,0,0); MIDC(1,1,0,1,1); MIDC(2,2,0,10,2); MIDC(3,3,0,35,3);
    __syncthreads();
    matmul_l<0,4>(sMid,sPart,g_wt+0,     o2+AOFF(0),tid);
    // ---- l = 1 ----
    MIDC(1,0,1,84,0); MIDC(1,1,1,87,1); MIDC(2,1,1,96,2);
    MIDC(2,2,1,111,3);MIDC(3,2,1,136,4);MIDC(3,3,1,171,5);
    __syncthreads();
    matmul_l<1,6>(sMid,sPart,g_wt+16384, o2+AOFF(1),tid);
    // ---- l = 2 ----
    MIDC(1,1,2,220,0);MIDC(2,0,2,229,1);MIDC(2,1,2,234,2);MIDC(2,2,2,249,3);
    MIDC(3,1,2,274,4);MIDC(3,2,2,295,5);MIDC(3,3,2,330,6);
    __syncthreads();
    matmul_l<2,7>(sMid,sPart,g_wt+40960, o2+AOFF(2),tid);
    // ---- l = 3 ----
    MIDC(2,1,3,379,0);MIDC(2,2,3,394,1);MIDC(3,0,3,419,2);
    MIDC(3,1,3,426,3);MIDC(3,2,3,447,4);MIDC(3,3,3,482,5);
    __syncthreads();
    matmul_l<3,6>(sMid,sPart,g_wt+69632, o2+AOFF(3),tid);
#undef MIDC
}

// ---------------- launch ----------------
extern "C" void kernel_launch(void* const* d_in, const int* in_sizes, int n_in,
                              void* d_out, int out_size){
    const float2* act = (const float2*)d_in[0];
    const float2* W   = (const float2*)d_in[1];
    const float*  bn  = (const float*)d_in[2];
    float2* out = (float2*)d_out;

    cudaFuncSetAttribute(k_main, cudaFuncAttributeMaxDynamicSharedMemorySize, SMEM_D_BYTES);

    init_cg   <<<23, 64>>>();
    zero_sumsq<<<(NCH+255)/256, 256>>>();
    k_sumsq   <<<NBATCH/NB_B, 256>>>(act);
    k_prep_w  <<<(NW+255)/256, 256>>>(W, bn);
    k_main    <<<NBATCH, 256, SMEM_D_BYTES>>>(act, out);
    (void)in_sizes; (void)n_in; (void)out_size;
}

// round 5
// speedup vs baseline: 1.0790x; 1.0790x over previous
#include <cuda_runtime.h>
#include <math.h>

typedef unsigned long long ull;

// ---------------- constants ----------------
#define NB_B 8
constexpr int NBATCH = 2048;
constexpr int CGTOT  = 531;
constexpr int NCH    = 5888;
constexpr int NW     = 94208;

__constant__ int c_l1[23]  = {0,1,2,3, 1,1,2,2,3,3, 1,2,2,2,3,3,3, 2,2,3,3,3,3};
__constant__ int c_l2[23]  = {0,1,2,3, 0,1,1,2,2,3, 1,0,1,2,1,2,3, 1,2,0,1,2,3};
__constant__ int c_lo[23]  = {0,0,0,0, 1,1,1,1,1,1, 2,2,2,2,2,2,2, 3,3,3,3,3,3};
__constant__ int c_off[23] = {0,1,10,35, 84,87,96,111,136,171,
                              220,229,234,249,274,295,330, 379,394,419,426,447,482};

__device__ float  g_cg[CGTOT];
__device__ float  g_sumsq[NCH];
__device__ float2 g_wt[NW];   // folded, transposed weights: [l-block][c][o]

__host__ __device__ constexpr int AOFF(int l){ return l==0?0 : l==1?16 : l==2?64 : 144; }

// ---------------- packed f32x2 helpers ----------------
__device__ __forceinline__ ull pk(float a, float b){
    ull r; asm("mov.b64 %0, {%1, %2};" : "=l"(r) : "f"(a), "f"(b)); return r;
}
__device__ __forceinline__ float2 unpk(ull v){
    float2 r; asm("mov.b64 {%0, %1}, %2;" : "=f"(r.x), "=f"(r.y) : "l"(v)); return r;
}
__device__ __forceinline__ ull fma2(ull a, ull b, ull c){
    ull d; asm("fma.rn.f32x2 %0, %1, %2, %3;" : "=l"(d) : "l"(a), "l"(b), "l"(c)); return d;
}
__device__ __forceinline__ ull mul2(ull a, ull b){
    ull d; asm("mul.rn.f32x2 %0, %1, %2;" : "=l"(d) : "l"(a), "l"(b)); return d;
}
// combine deferred complex accumulators: (A.x-B.y, A.y+B.x)
__device__ __forceinline__ float2 cmb(ull A, ull B){
    float2 a=unpk(A), b=unpk(B);
    return make_float2(a.x-b.y, a.y+b.x);
}

// ---------------- CG coefficient init (on device, fp64) ----------------
__device__ double d_fact(int n){ double r=1.0; for(int i=2;i<=n;++i) r*=(double)i; return r; }

__device__ double d_cg(int l1,int m1,int l2,int m2,int l,int m){
    if (m1+m2!=m) return 0.0;
    double pre = sqrt((double)(2*l+1)*d_fact(l1+l2-l)*d_fact(l1-l2+l)*d_fact(-l1+l2+l)/d_fact(l1+l2+l+1));
    pre *= sqrt(d_fact(l+m)*d_fact(l-m)*d_fact(l1-m1)*d_fact(l1+m1)*d_fact(l2-m2)*d_fact(l2+m2));
    double s=0.0;
    for(int k=0;k<=l1+l2-l;++k){
        int d0=k,d1=l1+l2-l-k,d2=l1-m1-k,d3=l2+m2-k,d4=l-l2+m1+k,d5=l-l1-m2+k;
        if(d0<0||d1<0||d2<0||d3<0||d4<0||d5<0) continue;
        double den=d_fact(d0)*d_fact(d1)*d_fact(d2)*d_fact(d3)*d_fact(d4)*d_fact(d5);
        s += ((k&1)? -1.0 : 1.0)/den;
    }
    return pre*s;
}

__global__ void init_cg(){
    int k = blockIdx.x;
    int l1=c_l1[k], l2=c_l2[k], l=c_lo[k];
    int n1=2*l1+1, n2=2*l2+1;
    for(int e=threadIdx.x; e<n1*n2; e+=blockDim.x){
        int m1=e/n2 - l1, m2=e%n2 - l2, m=m1+m2;
        float v=0.f;
        if (m>=-l && m<=l) v=(float)d_cg(l1,m1,l2,m2,l,m);
        g_cg[c_off[k]+e]=v;
    }
}

__global__ void zero_sumsq(){
    int i=blockIdx.x*blockDim.x+threadIdx.x;
    if(i<NCH) g_sumsq[i]=0.f;
}

// ---------------- mid tensor (packed): deferred accumulators A,B ----------------
// mid_r[p] = A[p].x - B[p].y ; mid_i[p] = A[p].y + B[p].x
template<int L1,int L2,int LO>
__device__ __forceinline__ void mid_ts2(const float2* __restrict__ a1,
                                        const float2* __restrict__ a2,
                                        const ull* __restrict__ cg2,
                                        ull (&A)[2*LO+1], ull (&Bv)[2*LO+1]){
    float2 f1[2*L1+1];
    ull f2p[2*L2+1];
#pragma unroll
    for(int i=0;i<2*L1+1;++i) f1[i]=a1[i];
#pragma unroll
    for(int j=0;j<2*L2+1;++j) f2p[j]=*reinterpret_cast<const ull*>(a2+j);
#pragma unroll
    for(int p=0;p<2*LO+1;++p){ A[p]=0ull; Bv[p]=0ull; }
#pragma unroll
    for(int i=0;i<2*L1+1;++i){
        ull f1x = pk(f1[i].x, f1[i].x);
        ull f1y = pk(f1[i].y, f1[i].y);
#pragma unroll
        for(int j=0;j<2*L2+1;++j){
            int m=(i-L1)+(j-L2);
            if (m < -LO || m > LO) continue;
            int p=m+LO;
            ull cp = cg2[i*(2*L2+1)+j];          // broadcast LDS.64 of (c,c)
            A[p]  = fma2(cp, mul2(f1x, f2p[j]), A[p]);
            Bv[p] = fma2(cp, mul2(f1y, f2p[j]), Bv[p]);
        }
    }
}

// ---------------- phase 1: per-channel sum of |mid|^2 over batch & p ----------------
__global__ __launch_bounds__(256) void k_sumsq(const float2* __restrict__ act){
    __shared__ float2 sAct[NB_B*256];
    __shared__ ull    sCg2[CGTOT];
    const int tid=threadIdx.x, t=tid>>4, s=tid&15;
    const float2* A = act + (size_t)blockIdx.x*NB_B*256;
    for(int i=tid;i<NB_B*256;i+=256) sAct[i]=A[i];
    for(int i=tid;i<CGTOT;i+=256){ float v=g_cg[i]; sCg2[i]=pk(v,v); }
    __syncthreads();

#define SQC(L1,L2,LO,CGOFF,CH0) do{                                            \
    float ssum=0.f;                                                            \
    _Pragma("unroll 1")                                                        \
    for(int b=0;b<NB_B;++b){                                                   \
        const float2* Ab=sAct+b*256;                                           \
        ull aA[2*(LO)+1], aB[2*(LO)+1];                                        \
        mid_ts2<L1,L2,LO>(Ab+AOFF(L1)+t*(2*(L1)+1),                            \
                          Ab+AOFF(L2)+s*(2*(L2)+1), sCg2+(CGOFF), aA, aB);     \
        _Pragma("unroll")                                                      \
        for(int p=0;p<2*(LO)+1;++p){                                           \
            float2 v=cmb(aA[p],aB[p]);                                         \
            ssum = fmaf(v.x,v.x,fmaf(v.y,v.y,ssum));                           \
        }                                                                      \
    }                                                                          \
    atomicAdd(&g_sumsq[(CH0)+t*16+s], ssum);                                   \
}while(0)

    SQC(0,0,0,0,0);     SQC(1,1,0,1,256);   SQC(2,2,0,10,512);  SQC(3,3,0,35,768);
    SQC(1,0,1,84,1024); SQC(1,1,1,87,1280); SQC(2,1,1,96,1536);
    SQC(2,2,1,111,1792);SQC(3,2,1,136,2048);SQC(3,3,1,171,2304);
    SQC(1,1,2,220,2560);SQC(2,0,2,229,2816);SQC(2,1,2,234,3072);SQC(2,2,2,249,3328);
    SQC(3,1,2,274,3584);SQC(3,2,2,295,3840);SQC(3,3,2,330,4096);
    SQC(2,1,3,379,4352);SQC(2,2,3,394,4608);SQC(3,0,3,419,4864);
    SQC(3,1,3,426,5120);SQC(3,2,3,447,5376);SQC(3,3,3,482,5632);
#undef SQC
}

// ---------------- fold batchnorm std into W, transpose to [c][o] ----------------
__global__ void k_prep_w(const float2* __restrict__ W, const float* __restrict__ bn){
    int w = blockIdx.x*blockDim.x+threadIdx.x;
    if (w>=NW) return;
    int l,wst,sst,Ml;
    if      (w<16384){l=0;wst=0;    sst=0;   Ml=1024;}
    else if (w<40960){l=1;wst=16384;sst=1024;Ml=1536;}
    else if (w<69632){l=2;wst=40960;sst=2560;Ml=1792;}
    else             {l=3;wst=69632;sst=4352;Ml=1536;}
    int r=w-wst, o=r/Ml, c=r%Ml;
    float bstd = sqrtf(g_sumsq[sst+c]/(float)(NBATCH*(2*l+1)));
    float nstd = (bn[sst+c]*1.0f + bstd)*0.5f;          // BM_CNT = 1
    float inv  = 1.0f/(nstd + 1e-5f);
    float2 wv = W[w];
    g_wt[wst + c*16 + o] = make_float2(wv.x*inv, wv.y*inv);
}

// ---------------- phase 2: main fused kernel ----------------
template<int LO,int NPAIR>
__device__ __forceinline__ void matmul_l(const float2* __restrict__ sMid,
                                         float2* sPart,
                                         const float2* __restrict__ wt,
                                         float2* __restrict__ outp, int tid){
    constexpr int NP = 2*LO+1;
    constexpr int CN = NPAIR*256/16;
    const int o = tid&15, g = tid>>4;
    ull accA[NP], accB[NP];
#pragma unroll
    for(int p=0;p<NP;++p){ accA[p]=0ull; accB[p]=0ull; }
    const float2* w = wt + (size_t)(g*CN)*16 + o;
    const ull* m = reinterpret_cast<const ull*>(sMid) + (size_t)(g*CN)*NP;
#pragma unroll 4
    for(int c=0;c<CN;++c){
        float2 wv = __ldg(&w[c*16]);
        ull wr = pk(wv.x, wv.x);
        ull wi = pk(wv.y, wv.y);
#pragma unroll
        for(int p=0;p<NP;++p){
            ull mv = m[c*NP+p];
            accA[p] = fma2(wr, mv, accA[p]);
            accB[p] = fma2(wi, mv, accB[p]);
        }
    }
#pragma unroll
    for(int p=0;p<NP;++p) sPart[(g*16+o)*NP+p]=cmb(accA[p],accB[p]);
    __syncthreads();
    if (tid < 16*NP){
        int oo=tid/NP, pp=tid%NP;
        float2 r=make_float2(0.f,0.f);
#pragma unroll
        for(int g2=0;g2<16;++g2){
            float2 v=sPart[(g2*16+oo)*NP+pp];
            r.x+=v.x; r.y+=v.y;
        }
        outp[oo*NP+pp]=r;
    }
    __syncthreads();
}

// dyn smem layout (all 8B-aligned):
//   sAct : 256 float2            = 2048  B  @ 0
//   sCg2 : 531 ull               = 4248  B  @ 2048
//   sMid : 10752 float2 (max l)  = 86016 B  @ 6296
//   sPart: 1792 float2           = 14336 B  @ 92312
constexpr int SMEM_D_BYTES = 2048 + 4248 + 86016 + 14336;   // 106,648 B

__global__ __launch_bounds__(256,2) void k_main(const float2* __restrict__ act,
                                                float2* __restrict__ out){
    extern __shared__ char dyn[];
    float2* sAct  = (float2*)(dyn);
    ull*    sCg2  = (ull*)(dyn + 2048);
    float2* sMid  = (float2*)(dyn + 6296);
    float2* sPart = (float2*)(dyn + 92312);
    const int tid=threadIdx.x, t=tid>>4, s=tid&15;
    sAct[tid] = act[(size_t)blockIdx.x*256 + tid];
    for(int i=tid;i<CGTOT;i+=256){ float v=g_cg[i]; sCg2[i]=pk(v,v); }
    __syncthreads();
    float2* o2 = out + (size_t)blockIdx.x*256;

#define MIDC(L1,L2,LO,CGOFF,PAIR) do{                                          \
    ull aA[2*(LO)+1], aB[2*(LO)+1];                                            \
    mid_ts2<L1,L2,LO>(sAct+AOFF(L1)+t*(2*(L1)+1),                              \
                      sAct+AOFF(L2)+s*(2*(L2)+1), sCg2+(CGOFF), aA, aB);       \
    float2* mp=sMid+((PAIR)*256+(t*16+s))*(2*(LO)+1);                          \
    _Pragma("unroll")                                                          \
    for(int p=0;p<2*(LO)+1;++p) mp[p]=cmb(aA[p],aB[p]);                        \
}while(0)

    // ---- l = 0 ----
    MIDC(0,0,0,0,0); MIDC(1,1,0,1,1); MIDC(2,2,0,10,2); MIDC(3,3,0,35,3);
    __syncthreads();
    matmul_l<0,4>(sMid,sPart,g_wt+0,     o2+AOFF(0),tid);
    // ---- l = 1 ----
    MIDC(1,0,1,84,0); MIDC(1,1,1,87,1); MIDC(2,1,1,96,2);
    MIDC(2,2,1,111,3);MIDC(3,2,1,136,4);MIDC(3,3,1,171,5);
    __syncthreads();
    matmul_l<1,6>(sMid,sPart,g_wt+16384, o2+AOFF(1),tid);
    // ---- l = 2 ----
    MIDC(1,1,2,220,0);MIDC(2,0,2,229,1);MIDC(2,1,2,234,2);MIDC(2,2,2,249,3);
    MIDC(3,1,2,274,4);MIDC(3,2,2,295,5);MIDC(3,3,2,330,6);
    __syncthreads();
    matmul_l<2,7>(sMid,sPart,g_wt+40960, o2+AOFF(2),tid);
    // ---- l = 3 ----
    MIDC(2,1,3,379,0);MIDC(2,2,3,394,1);MIDC(3,0,3,419,2);
    MIDC(3,1,3,426,3);MIDC(3,2,3,447,4);MIDC(3,3,3,482,5);
    __syncthreads();
    matmul_l<3,6>(sMid,sPart,g_wt+69632, o2+AOFF(3),tid);
#undef MIDC
}

// ---------------- launch ----------------
extern "C" void kernel_launch(void* const* d_in, const int* in_sizes, int n_in,
                              void* d_out, int out_size){
    const float2* act = (const float2*)d_in[0];
    const float2* W   = (const float2*)d_in[1];
    const float*  bn  = (const float*)d_in[2];
    float2* out = (float2*)d_out;

    cudaFuncSetAttribute(k_main, cudaFuncAttributeMaxDynamicSharedMemorySize, SMEM_D_BYTES);

    init_cg   <<<23, 64>>>();
    zero_sumsq<<<(NCH+255)/256, 256>>>();
    k_sumsq   <<<NBATCH/NB_B, 256>>>(act);
    k_prep_w  <<<(NW+255)/256, 256>>>(W, bn);
    k_main    <<<NBATCH, 256, SMEM_D_BYTES>>>(act, out);
    (void)in_sizes; (void)n_in; (void)out_size;
}